// round 16
// baseline (speedup 1.0000x reference)
#include <cuda_runtime.h>
#include <cuda_bf16.h>
#include <cuda_fp16.h>
#include <cstdint>

#define BB 64
#define SS 1024
#define HH 1024
#define NSC 8

// ---------------- scratch (device globals; no runtime allocation) ------------------
__device__ __align__(16) float g_q[BB*HH];
__device__ __align__(16) float g_qk[BB*HH];
__device__ __align__(16) float g_logits[BB*SS];
__device__ __align__(16) float g_attn[BB*SS];
__device__ __align__(16) float g_pyr[(size_t)BB*510*HH];        // block-sum pyramid
__device__ __align__(16) __half g_pooledh[(size_t)32768*HH];    // padded per-scale, fp16
__device__ __align__(16) float g_feat[(size_t)32768*HH];        // padded per-scale
__device__ __align__(16) __half g_WpTh[(size_t)NSC*HH*HH];      // Wp^T [i][n][k], fp16
__device__              float g_si[BB*NSC];
__device__ __align__(16) float g_ctx[(size_t)BB*NSC*HH];
__device__ __align__(16) float g_xa[BB*HH];
__device__ __align__(16) float g_bc[BB*HH];

// scale i: n_i = {1,3,7,15,31,63,127,255}; padded row offsets (multiples of 256)
__constant__ int c_n[8]    = {1,3,7,15,31,63,127,255};
__constant__ int c_PO[8]   = {0,256,512,1024,2048,4096,8192,16384};
__constant__ int c_loff[8] = {0,256,384,448,480,496,504,508};

// ---------------- cp.async / ldmatrix helpers --------------------------------------
__device__ __forceinline__ void cp_async16(void* smem_dst, const void* gmem_src) {
    unsigned dst = (unsigned)__cvta_generic_to_shared(smem_dst);
    asm volatile("cp.async.ca.shared.global [%0], [%1], 16;\n" :: "r"(dst), "l"(gmem_src));
}
__device__ __forceinline__ void cp_async_commit() {
    asm volatile("cp.async.commit_group;\n");
}
template<int N>
__device__ __forceinline__ void cp_async_wait() {
    asm volatile("cp.async.wait_group %0;\n" :: "n"(N));
}
__device__ __forceinline__ void ldsm_x4(unsigned& r0, unsigned& r1, unsigned& r2,
                                        unsigned& r3, uint32_t a) {
    asm volatile("ldmatrix.sync.aligned.m8n8.x4.shared.b16 {%0,%1,%2,%3}, [%4];"
                 : "=r"(r0), "=r"(r1), "=r"(r2), "=r"(r3) : "r"(a));
}

// ---------------- 256-thread GEMM body: C[64,1024] = A@B + bias --------------------
// bid2 in [0,32): bx=bid2&3 -> 256 cols, by=bid2>>2 -> 8 rows
__device__ __forceinline__ void sgemm256_body(const float* A, size_t lda,
                                              const float* __restrict__ Bm,
                                              const float* __restrict__ bias,
                                              float* __restrict__ C,
                                              int bid2, float* As /* 8*1024 */)
{
    int tid = threadIdx.x;
    int bx = bid2 & 3, by = bid2 >> 2;
    int r0 = by * 8;
    int n  = bx * 256 + tid;
    for (int idx = tid; idx < 8*1024; idx += 256) {
        int r = idx >> 10, k = idx & 1023;
        As[r * 1024 + k] = A[(size_t)(r0 + r) * lda + k];
    }
    __syncthreads();
    float acc[8] = {0,0,0,0,0,0,0,0};
    #pragma unroll 4
    for (int k = 0; k < 1024; k++) {
        float bv = Bm[(size_t)k * 1024 + n];
        #pragma unroll
        for (int r = 0; r < 8; r++) acc[r] += As[r * 1024 + k] * bv;
    }
    float bb = bias[n];
    #pragma unroll
    for (int r = 0; r < 8; r++) C[(size_t)(r0 + r) * 1024 + n] = acc[r] + bb;
}

// ---------------- pyramid level body (one (j,b) pair, 256 threads) -----------------
__device__ __forceinline__ void pyr_body(int l, int j, int b, int Rm1)
{
    int tid = threadIdx.x;
    int i = 7 - l;
    float inv = 1.f / (float)(8 << l);
    const float4* P = (const float4*)g_pyr;
    size_t base = ((size_t)b * 510 + c_loff[l]) * 256;
    float4 r0 = P[base + (size_t)j * 256 + tid];
    float4 r1 = P[base + (size_t)(j + 1) * 256 + tid];
    float4 s = { r0.x + r1.x, r0.y + r1.y, r0.z + r1.z, r0.w + r1.w };
    __half2 h01 = __floats2half2_rn(s.x * inv, s.y * inv);
    __half2 h23 = __floats2half2_rn(s.z * inv, s.w * inv);
    uint2 packed = { *(unsigned*)&h01, *(unsigned*)&h23 };
    ((uint2*)g_pooledh)[(size_t)(c_PO[i] + b * Rm1 + j) * 256 + tid] = packed;
    if (l < 7 && (j & 1) == 0) {
        size_t nbase = ((size_t)b * 510 + c_loff[l + 1]) * 256;
        ((float4*)g_pyr)[nbase + (size_t)(j >> 1) * 256 + tid] = s;
    }
}

// ---------------- L1: wpt (8192) ∪ q_gemm (32) ∪ si (64) ---------------------------
__global__ void __launch_bounds__(256) k_mega1(
    const float* __restrict__ x,  const float* __restrict__ Wq,
    const float* __restrict__ bq, const float* __restrict__ Ws,
    const float* __restrict__ bs, const float* __restrict__ Wp)
{
    __shared__ float sb[8*1024];
    int bid = blockIdx.x, tid = threadIdx.x;
    if (bid < 8192) {
        // Wp transpose+convert: WpTh[i][n][k] = half(Wp[i][k][n])
        float (*t)[33] = (float(*)[33])sb;
        int i = bid >> 10, kb = (bid >> 5) & 31, nb = bid & 31;
        int k0 = kb * 32, n0 = nb * 32;
        const float* src = Wp + (size_t)i * 1048576;
        __half* dst = g_WpTh + (size_t)i * 1048576;
        int tx = tid & 31, ty = tid >> 5;   // 32 x 8
        #pragma unroll
        for (int r = 0; r < 32; r += 8)
            t[ty + r][tx] = src[(size_t)(k0 + ty + r) * 1024 + n0 + tx];
        __syncthreads();
        #pragma unroll
        for (int r = 0; r < 32; r += 8)
            dst[(size_t)(n0 + ty + r) * 1024 + k0 + tx] = __float2half_rn(t[tx][ty + r]);
    } else if (bid < 8224) {
        // q = x_last @ Wq + bq
        sgemm256_body(x + (size_t)(SS - 1) * HH, (size_t)SS * HH, Wq, bq, g_q,
                      bid - 8192, sb);
    } else {
        // scale_importance = softmax(x_last @ Ws + bs)
        int b = bid - 8224;
        float* xl = sb;            // 1024
        float* red = sb + 1024;    // 256
        const float* xp = x + ((size_t)b * SS + SS - 1) * HH;
        for (int k = tid; k < HH; k += 256) xl[k] = xp[k];
        __syncthreads();
        int n = tid & 7, g = tid >> 3;    // g: 0..31
        float s = 0.f;
        for (int k = g; k < HH; k += 32) s += xl[k] * Ws[k * NSC + n];
        red[tid] = s; __syncthreads();
        for (int st = 16; st >= 1; st >>= 1) {
            if (g < st) red[tid] += red[tid + st * 8];
            __syncthreads();
        }
        if (tid == 0) {
            float l[8], mx = -1e30f;
            #pragma unroll
            for (int j = 0; j < 8; j++) { l[j] = red[j] + bs[j]; mx = fmaxf(mx, l[j]); }
            float sum = 0.f;
            #pragma unroll
            for (int j = 0; j < 8; j++) { l[j] = __expf(l[j] - mx); sum += l[j]; }
            #pragma unroll
            for (int j = 0; j < 8; j++) g_si[b * 8 + j] = l[j] / sum;
        }
    }
}

// ---------------- qk[b,j] = sum_h Wk[j,h] * q[b,h] ---------------------------------
__global__ void k_qk(const float* __restrict__ Wk)
{
    __shared__ float qsm[8][1024];
    __shared__ float wt[128][17];
    int j0 = blockIdx.x * 128, b0 = blockIdx.y * 8, tid = threadIdx.x;
    for (int idx = tid; idx < 8*1024; idx += 128) {
        int r = idx >> 10, k = idx & 1023;
        qsm[r][k] = g_q[(b0 + r) * HH + k];
    }
    float acc[8] = {0,0,0,0,0,0,0,0};
    for (int h0 = 0; h0 < 1024; h0 += 16) {
        __syncthreads();
        for (int idx = tid; idx < 128*16; idx += 128) {
            int r = idx >> 4, c = idx & 15;
            wt[r][c] = Wk[(size_t)(j0 + r) * HH + h0 + c];
        }
        __syncthreads();
        #pragma unroll
        for (int h = 0; h < 16; h++) {
            float wv = wt[tid][h];
            #pragma unroll
            for (int r = 0; r < 8; r++) acc[r] += qsm[r][h0 + h] * wv;
        }
    }
    #pragma unroll
    for (int r = 0; r < 8; r++) g_qk[(b0 + r) * HH + j0 + tid] = acc[r];
}

// ---------------- pass 1: logits (x . qk) + stride-4 block sums --------------------
__global__ void k_pass1(const float* __restrict__ x)
{
    int m = blockIdx.x, b = blockIdx.y, tid = threadIdx.x;  // 256 threads
    const float4* xp = (const float4*)(x + ((size_t)b * SS + m * 4) * HH);
    float4 qk4 = ((const float4*)g_qk)[b * 256 + tid];
    float4 cs = {0.f,0.f,0.f,0.f};
    float dt[4];
    #pragma unroll
    for (int s = 0; s < 4; s++) {
        float4 v = xp[s * 256 + tid];
        cs.x += v.x; cs.y += v.y; cs.z += v.z; cs.w += v.w;
        dt[s] = v.x*qk4.x + v.y*qk4.y + v.z*qk4.z + v.w*qk4.w;
    }
    ((float4*)g_pyr)[((size_t)b * 510 + m) * 256 + tid] = cs;
    #pragma unroll
    for (int o = 16; o; o >>= 1) {
        dt[0] += __shfl_down_sync(0xffffffffu, dt[0], o);
        dt[1] += __shfl_down_sync(0xffffffffu, dt[1], o);
        dt[2] += __shfl_down_sync(0xffffffffu, dt[2], o);
        dt[3] += __shfl_down_sync(0xffffffffu, dt[3], o);
    }
    __shared__ float wr[8][4];
    int lane = tid & 31, warp = tid >> 5;
    if (lane == 0) { wr[warp][0]=dt[0]; wr[warp][1]=dt[1]; wr[warp][2]=dt[2]; wr[warp][3]=dt[3]; }
    __syncthreads();
    if (tid < 4) {
        float s = 0.f;
        #pragma unroll
        for (int w = 0; w < 8; w++) s += wr[w][tid];
        g_logits[b * SS + m * 4 + tid] = s;
    }
}

// ---------------- L4: softmax (64) ∪ pyr level 0 (255*64) --------------------------
__global__ void __launch_bounds__(256) k_sm_pyr0()
{
    __shared__ float red[256];
    int bid = blockIdx.x, tid = threadIdx.x;
    if (bid < 64) {
        int b = bid;
        float4 v = ((const float4*)g_logits)[b * 256 + tid];
        const float sc = 0.03125f;               // 1/sqrt(H*T)
        v.x *= sc; v.y *= sc; v.z *= sc; v.w *= sc;
        float mx = fmaxf(fmaxf(v.x, v.y), fmaxf(v.z, v.w));
        red[tid] = mx; __syncthreads();
        for (int st = 128; st; st >>= 1) { if (tid < st) red[tid] = fmaxf(red[tid], red[tid + st]); __syncthreads(); }
        mx = red[0]; __syncthreads();
        float4 e = { __expf(v.x - mx), __expf(v.y - mx), __expf(v.z - mx), __expf(v.w - mx) };
        red[tid] = e.x + e.y + e.z + e.w; __syncthreads();
        for (int st = 128; st; st >>= 1) { if (tid < st) red[tid] += red[tid + st]; __syncthreads(); }
        float inv = 1.f / red[0];
        float4 o = { e.x*inv, e.y*inv, e.z*inv, e.w*inv };
        ((float4*)g_attn)[b * 256 + tid] = o;
    } else {
        int idx = bid - 64;
        pyr_body(0, idx % 255, idx / 255, 255);
    }
}

// ---------------- L5: pass2 (256) ∪ pyr level 1 (127*64) ---------------------------
__global__ void __launch_bounds__(256) k_p2_pyr1(const float* __restrict__ x)
{
    __shared__ float at[SS];
    int bid = blockIdx.x, tid = threadIdx.x;
    if (bid < 256) {
        int b = bid >> 2, c = bid & 3;
        for (int i = tid; i < SS; i += 256) at[i] = g_attn[b * SS + i];
        __syncthreads();
        int h = c * 256 + tid;
        const float* xp = x + (size_t)b * SS * HH + h;
        float a0=0.f, a1=0.f, a2=0.f, a3=0.f;
        #pragma unroll 2
        for (int s = 0; s < SS; s += 4) {
            a0 += at[s+0] * xp[(size_t)(s+0) * HH];
            a1 += at[s+1] * xp[(size_t)(s+1) * HH];
            a2 += at[s+2] * xp[(size_t)(s+2) * HH];
            a3 += at[s+3] * xp[(size_t)(s+3) * HH];
        }
        g_xa[b * HH + h] = (a0 + a1) + (a2 + a3);
    } else {
        int idx = bid - 256;
        pyr_body(1, idx % 127, idx / 127, 127);
    }
}

// ---------------- L6: bc_gemm (32) ∪ pyr level 2 (63*64) ---------------------------
__global__ void __launch_bounds__(256) k_bc_pyr2(const float* __restrict__ Wv,
                                                 const float* __restrict__ bv)
{
    __shared__ float As[8*1024];
    int bid = blockIdx.x;
    if (bid < 32) {
        sgemm256_body(g_xa, HH, Wv, bv, g_bc, bid, As);
    } else {
        int idx = bid - 32;
        pyr_body(2, idx % 63, idx / 63, 63);
    }
}

// ---------------- L7: pyramid ladder, levels 3..7 fused ----------------------------
// One block per (batch, 128-float h-chunk). Level-3 rows (32) live in smem;
// each level emits pooled rows (fp16) and halves the row count.
__global__ void __launch_bounds__(256) k_ladder()
{
    __shared__ float4 rows[32][32];     // 32 rows x 128 floats
    int tid = threadIdx.x;
    int b = blockIdx.x >> 3, ch = blockIdx.x & 7;
    int cq = ch * 32;                    // float4 column base within 256
    const float4* P = (const float4*)g_pyr;
    size_t base = ((size_t)b * 510 + 448) * 256;   // c_loff[3]
    #pragma unroll
    for (int u = 0; u < 4; u++) {
        int idx = tid + u * 256;
        int r = idx >> 5, q = idx & 31;
        rows[r][q] = P[base + (size_t)r * 256 + cq + q];
    }
    __syncthreads();

    int R = 32;
    #pragma unroll
    for (int l = 3; l < 8; l++) {
        int i = 7 - l;
        float inv = 1.f / (float)(8 << l);
        int nOut = R - 1;
        // pooled rows
        for (int idx = tid; idx < nOut * 32; idx += 256) {
            int j = idx >> 5, q = idx & 31;
            float4 a = rows[j][q], bq4 = rows[j + 1][q];
            float4 s = { a.x + bq4.x, a.y + bq4.y, a.z + bq4.z, a.w + bq4.w };
            __half2 h01 = __floats2half2_rn(s.x * inv, s.y * inv);
            __half2 h23 = __floats2half2_rn(s.z * inv, s.w * inv);
            uint2 packed = { *(unsigned*)&h01, *(unsigned*)&h23 };
            ((uint2*)g_pooledh)[(size_t)(c_PO[i] + b * nOut + j) * 256 + cq + q] = packed;
        }
        if (l < 7) {
            // next level: rows[j] = rows[2j] + rows[2j+1], j < R/2 (reg-buffered)
            float4 tmp[2];
            int cnt = (R / 2) * 32;
            int nmine = 0;
            for (int idx = tid; idx < cnt; idx += 256) {
                int j = idx >> 5, q = idx & 31;
                float4 a = rows[2*j][q], b4 = rows[2*j + 1][q];
                tmp[nmine].x = a.x + b4.x; tmp[nmine].y = a.y + b4.y;
                tmp[nmine].z = a.z + b4.z; tmp[nmine].w = a.w + b4.w;
                nmine++;
            }
            __syncthreads();
            nmine = 0;
            for (int idx = tid; idx < cnt; idx += 256) {
                int j = idx >> 5, q = idx & 31;
                rows[j][q] = tmp[nmine++];
            }
            __syncthreads();
        }
        R >>= 1;
    }
}

// ---------------- feat = tanh(pooled @ Wp[i] + bp[i]) ------------------------------
// mma.sync f16 m16n8k16 (fp32 accum), 128x128 block tile, 256 threads = 8 warps
// (2x4, warp tile 64x32), 4-stage cp.async ring (K-chunk 32 halfs), ldmatrix.x4.
#define KPH 40                         // 32 k halfs + 8 pad
#define STG_H (2 * 128 * KPH)          // halfs per stage (A then B) = 10240
#define F_SMEM_BYTES (4 * STG_H * 2)   // 81920 bytes

__global__ void __launch_bounds__(256, 2) k_feat(const float* __restrict__ bp)
{
    extern __shared__ __align__(16) __half smh[];
    int tid = threadIdx.x, lane = tid & 31, warp = tid >> 5;
    int wm = warp >> 2, wn = warp & 3;          // 2 x 4 warp grid, 64x32 per warp
    int grp = lane >> 2, tg = lane & 3;

    int ty = blockIdx.y;                         // 0..255 -> 128-row tile
    int n0 = blockIdx.x * 128;
    int r256 = ty >> 1;
    int i = r256 ? (32 - __clz(r256)) : 0;       // scale index (padded layout)
    size_t row0 = (size_t)ty * 128;

    const __half* Ab = g_pooledh + row0 * 1024;
    const __half* Bb = g_WpTh + (size_t)i * 1048576 + (size_t)n0 * 1024;

    // ldmatrix per-lane address offsets (bytes)
    int lj = lane >> 3, lr = lane & 7;
    uint32_t a_off = (uint32_t)(((((lj & 1) << 3) + lr) * KPH + ((lj >> 1) << 3)) * 2);
    uint32_t b_off = (uint32_t)(((((lj >> 1) << 3) + lr) * KPH + ((lj & 1) << 3)) * 2);
    uint32_t smbase = (uint32_t)__cvta_generic_to_shared(smh);
    uint32_t awarp = (uint32_t)(wm * 64 * KPH * 2) + a_off;
    uint32_t bwarp = (uint32_t)(wn * 32 * KPH * 2) + b_off;

    float acc[4][4][4];
    #pragma unroll
    for (int a = 0; a < 4; a++)
        #pragma unroll
        for (int b2 = 0; b2 < 4; b2++)
            #pragma unroll
            for (int c = 0; c < 4; c++) acc[a][b2][c] = 0.f;

    auto load_stage = [&](int st, int ch) {
        __half* As = smh + st * STG_H;
        __half* Bs = As + 128 * KPH;
        int k0 = ch * 32;
        #pragma unroll
        for (int j = 0; j < 2; j++) {
            int idx = tid + j * 256;
            int r = idx >> 2, c = (idx & 3) * 8;     // half units
            cp_async16(&As[r * KPH + c], Ab + (size_t)r * 1024 + k0 + c);
            cp_async16(&Bs[r * KPH + c], Bb + (size_t)r * 1024 + k0 + c);
        }
        cp_async_commit();
    };

    load_stage(0, 0);
    load_stage(1, 1);
    load_stage(2, 2);

    for (int ch = 0; ch < 32; ch++) {
        if (ch < 30)       cp_async_wait<2>();
        else if (ch == 30) cp_async_wait<1>();
        else               cp_async_wait<0>();
        __syncthreads();

        if (ch + 3 < 32) load_stage((ch + 3) & 3, ch + 3);

        uint32_t abase = smbase + (uint32_t)((ch & 3) * STG_H * 2) + awarp;
        uint32_t bbase = smbase + (uint32_t)((ch & 3) * STG_H * 2 + 128 * KPH * 2) + bwarp;

        #pragma unroll
        for (int ks = 0; ks < 2; ks++) {             // two k16 steps per chunk
            uint32_t koff = (uint32_t)(ks * 32);     // 16 halfs = 32 bytes
            unsigned a[4][4], bf[4][2];
            #pragma unroll
            for (int mt = 0; mt < 4; mt++)
                ldsm_x4(a[mt][0], a[mt][1], a[mt][2], a[mt][3],
                        abase + (uint32_t)(mt * 16 * KPH * 2) + koff);
            #pragma unroll
            for (int p = 0; p < 2; p++)
                ldsm_x4(bf[2*p][0], bf[2*p][1], bf[2*p+1][0], bf[2*p+1][1],
                        bbase + (uint32_t)(p * 16 * KPH * 2) + koff);
            #pragma unroll
            for (int mt = 0; mt < 4; mt++)
                #pragma unroll
                for (int nt = 0; nt < 4; nt++) {
                    asm volatile(
                        "mma.sync.aligned.m16n8k16.row.col.f32.f16.f16.f32 "
                        "{%0,%1,%2,%3}, {%4,%5,%6,%7}, {%8,%9}, {%0,%1,%2,%3};"
                        : "+f"(acc[mt][nt][0]), "+f"(acc[mt][nt][1]),
                          "+f"(acc[mt][nt][2]), "+f"(acc[mt][nt][3])
                        : "r"(a[mt][0]), "r"(a[mt][1]), "r"(a[mt][2]), "r"(a[mt][3]),
                          "r"(bf[nt][0]), "r"(bf[nt][1]));
                }
        }
    }

    const float* bias = bp + i * 1024 + n0;
    #pragma unroll
    for (int mt = 0; mt < 4; mt++)
        #pragma unroll
        for (int nt = 0; nt < 4; nt++) {
            int row  = (int)row0 + wm * 64 + mt * 16 + grp;
            int cloc = wn * 32 + nt * 8 + tg * 2;
            int col  = n0 + cloc;
            float b0v = bias[cloc], b1v = bias[cloc + 1];
            g_feat[(size_t)row * 1024 + col    ] = tanhf(acc[mt][nt][0] + b0v);
            g_feat[(size_t)row * 1024 + col + 1] = tanhf(acc[mt][nt][1] + b1v);
            g_feat[(size_t)(row + 8) * 1024 + col    ] = tanhf(acc[mt][nt][2] + b0v);
            g_feat[(size_t)(row + 8) * 1024 + col + 1] = tanhf(acc[mt][nt][3] + b1v);
        }
}

// ---------------- per-scale attention: fa = softmax(q.feat/32); ctx = fa.feat ------
__global__ void k_scale_attn()
{
    int i = blockIdx.x, b = blockIdx.y;      // 8 x 64
    int tid = threadIdx.x;                    // 256 threads
    int lane = tid & 31, warp = tid >> 5;
    int n_i = c_n[i];
    size_t rowbase = (size_t)c_PO[i] + (size_t)b * n_i;

    __shared__ float4 qs4[256];
    __shared__ float d[256];
    __shared__ float red[256];

    qs4[tid] = ((const float4*)g_q)[b * 256 + tid];
    __syncthreads();

    const float4* F = (const float4*)g_feat;
    for (int n = warp; n < n_i; n += 8) {
        const float4* fr = F + (rowbase + n) * 256;
        float s = 0.f;
        for (int h = lane; h < 256; h += 32) {
            float4 f = fr[h]; float4 qq = qs4[h];
            s += f.x*qq.x + f.y*qq.y + f.z*qq.z + f.w*qq.w;
        }
        #pragma unroll
        for (int o = 16; o; o >>= 1) s += __shfl_down_sync(0xffffffffu, s, o);
        if (lane == 0) d[n] = s * 0.03125f;
    }
    __syncthreads();

    float val = (tid < n_i) ? d[tid] : -1e30f;
    red[tid] = val; __syncthreads();
    for (int st = 128; st; st >>= 1) { if (tid < st) red[tid] = fmaxf(red[tid], red[tid + st]); __syncthreads(); }
    float mx = red[0]; __syncthreads();
    float e = (tid < n_i) ? __expf(val - mx) : 0.f;
    red[tid] = e; __syncthreads();
    for (int st = 128; st; st >>= 1) { if (tid < st) red[tid] += red[tid + st]; __syncthreads(); }
    float inv = 1.f / red[0];
    __syncthreads();
    if (tid < n_i) d[tid] = e * inv;
    __syncthreads();

    float4 acc = {0.f,0.f,0.f,0.f};
    for (int n = 0; n < n_i; n++) {
        float w = d[n];
        float4 f = F[(rowbase + n) * 256 + tid];
        acc.x += w*f.x; acc.y += w*f.y; acc.z += w*f.z; acc.w += w*f.w;
    }
    ((float4*)g_ctx)[(size_t)(b * 8 + i) * 256 + tid] = acc;
}

// ---------------- out = (bc + sum_i si*ctx_i) @ Wo + bo (combine fused) ------------
__global__ void __launch_bounds__(256) k_out_gemm(const float* __restrict__ Wo,
                                                  const float* __restrict__ bo,
                                                  float* __restrict__ out)
{
    __shared__ float As[8*1024];
    int tid = threadIdx.x;
    int bx = blockIdx.x & 3, by = blockIdx.x >> 2;
    int r0 = by * 8;
    int n  = bx * 256 + tid;
    for (int idx = tid; idx < 8*1024; idx += 256) {
        int r = idx >> 10, k = idx & 1023;
        int row = r0 + r;
        float v = g_bc[(size_t)row * 1024 + k];
        #pragma unroll
        for (int i = 0; i < 8; i++)
            v += g_si[row * 8 + i] * g_ctx[(size_t)(row * 8 + i) * 1024 + k];
        As[r * 1024 + k] = v;
    }
    __syncthreads();
    float acc[8] = {0,0,0,0,0,0,0,0};
    #pragma unroll 4
    for (int k = 0; k < 1024; k++) {
        float bv = Wo[(size_t)k * 1024 + n];
        #pragma unroll
        for (int r = 0; r < 8; r++) acc[r] += As[r * 1024 + k] * bv;
    }
    float bb = bo[n];
    #pragma unroll
    for (int r = 0; r < 8; r++) out[(size_t)(r0 + r) * 1024 + n] = acc[r] + bb;
}

// -----------------------------------------------------------------------------------
extern "C" void kernel_launch(void* const* d_in, const int* in_sizes, int n_in,
                              void* d_out, int out_size)
{
    const float* x  = (const float*)d_in[0];
    const float* Wq = (const float*)d_in[1];
    const float* bq = (const float*)d_in[2];
    const float* Wk = (const float*)d_in[3];
    // bk (d_in[4]) cancels inside softmax — unused
    const float* Wv = (const float*)d_in[5];
    const float* bv = (const float*)d_in[6];
    const float* Wp = (const float*)d_in[7];
    const float* bp = (const float*)d_in[8];
    const float* Ws = (const float*)d_in[9];
    const float* bs = (const float*)d_in[10];
    const float* Wo = (const float*)d_in[11];
    const float* bo = (const float*)d_in[12];
    float* out = (float*)d_out;

    cudaFuncSetAttribute(k_feat, cudaFuncAttributeMaxDynamicSharedMemorySize, F_SMEM_BYTES);

    k_mega1     <<<8288, 256>>>(x, Wq, bq, Ws, bs, Wp);        // wpt ∪ q_gemm ∪ si
    k_qk        <<<dim3(8, 8), 128>>>(Wk);
    k_pass1     <<<dim3(256, 64), 256>>>(x);
    k_sm_pyr0   <<<64 + 255*64, 256>>>();                       // softmax ∪ pyr l0
    k_p2_pyr1   <<<256 + 127*64, 256>>>(x);                     // pass2 ∪ pyr l1
    k_bc_pyr2   <<<32 + 63*64, 256>>>(Wv, bv);                  // bc_gemm ∪ pyr l2
    k_ladder    <<<512, 256>>>();                               // pyr l3..l7
    k_feat      <<<dim3(8, 256), 256, F_SMEM_BYTES>>>(bp);
    k_scale_attn<<<dim3(8, 64), 256>>>();
    k_out_gemm  <<<32, 256>>>(Wo, bo, out);                     // combine fused in
}

// round 17
// speedup vs baseline: 1.1392x; 1.1392x over previous
#include <cuda_runtime.h>
#include <cuda_bf16.h>
#include <cuda_fp16.h>
#include <cstdint>

#define BB 64
#define SS 1024
#define HH 1024
#define NSC 8

// ---------------- scratch (device globals; no runtime allocation) ------------------
__device__ __align__(16) float g_q[BB*HH];
__device__ __align__(16) float g_qk[BB*HH];
__device__ __align__(16) float g_logits[BB*SS];
__device__ __align__(16) float g_attn[BB*SS];
__device__ __align__(16) float g_pyr[(size_t)BB*510*HH];        // block-sum pyramid
__device__ __align__(16) __half g_pooledh[(size_t)32768*HH];    // padded per-scale, fp16
__device__ __align__(16) float g_feat[(size_t)32768*HH];        // padded per-scale
__device__ __align__(16) __half g_WpTh[(size_t)NSC*HH*HH];      // Wp^T [i][n][k], fp16
__device__              float g_si[BB*NSC];
__device__ __align__(16) float g_ctx[(size_t)BB*NSC*HH];
__device__ __align__(16) float g_xa[BB*HH];
__device__ __align__(16) float g_bc[BB*HH];

// scale i: n_i = {1,3,7,15,31,63,127,255}; padded row offsets (multiples of 256)
__constant__ int c_n[8]    = {1,3,7,15,31,63,127,255};
__constant__ int c_PO[8]   = {0,256,512,1024,2048,4096,8192,16384};
__constant__ int c_loff[8] = {0,256,384,448,480,496,504,508};

// ---------------- cp.async / ldmatrix helpers --------------------------------------
__device__ __forceinline__ void cp_async16(void* smem_dst, const void* gmem_src) {
    unsigned dst = (unsigned)__cvta_generic_to_shared(smem_dst);
    asm volatile("cp.async.ca.shared.global [%0], [%1], 16;\n" :: "r"(dst), "l"(gmem_src));
}
__device__ __forceinline__ void cp_async_commit() {
    asm volatile("cp.async.commit_group;\n");
}
template<int N>
__device__ __forceinline__ void cp_async_wait() {
    asm volatile("cp.async.wait_group %0;\n" :: "n"(N));
}
__device__ __forceinline__ void ldsm_x4(unsigned& r0, unsigned& r1, unsigned& r2,
                                        unsigned& r3, uint32_t a) {
    asm volatile("ldmatrix.sync.aligned.m8n8.x4.shared.b16 {%0,%1,%2,%3}, [%4];"
                 : "=r"(r0), "=r"(r1), "=r"(r2), "=r"(r3) : "r"(a));
}

// ---------------- small GEMM body: C[64,1024] = A[64,1024]@B[1024,1024] + bias -----
__device__ __forceinline__ void sgemm_rowB_body(const float* A, size_t lda,
                                                const float* __restrict__ Bm,
                                                const float* __restrict__ bias,
                                                float* __restrict__ C)
{
    __shared__ float As[8][1024];
    int r0 = blockIdx.y * 8;
    int n  = blockIdx.x * 128 + threadIdx.x;
    for (int idx = threadIdx.x; idx < 8*1024; idx += 128) {
        int r = idx >> 10, k = idx & 1023;
        As[r][k] = A[(size_t)(r0 + r) * lda + k];
    }
    __syncthreads();
    float acc[8] = {0,0,0,0,0,0,0,0};
    #pragma unroll 4
    for (int k = 0; k < 1024; k++) {
        float bv = Bm[(size_t)k * 1024 + n];
        #pragma unroll
        for (int r = 0; r < 8; r++) acc[r] += As[r][k] * bv;
    }
    float bb = bias[n];
    #pragma unroll
    for (int r = 0; r < 8; r++) C[(size_t)(r0 + r) * 1024 + n] = acc[r] + bb;
}

__global__ void k_q_gemm(const float* __restrict__ x, const float* __restrict__ Wq,
                         const float* __restrict__ bq)
{   sgemm_rowB_body(x + (size_t)(SS - 1) * HH, (size_t)SS * HH, Wq, bq, g_q); }
__global__ void k_bc_gemm(const float* __restrict__ Wv, const float* __restrict__ bv)
{   sgemm_rowB_body(g_xa, HH, Wv, bv, g_bc); }

// ---------------- Wp transpose+convert: WpTh[i][n][k] = half(Wp[i][k][n]) ----------
__global__ void k_wpt(const float* __restrict__ Wp)
{
    __shared__ float t[32][33];
    int i = blockIdx.z;
    int k0 = blockIdx.y * 32, n0 = blockIdx.x * 32;
    const float* src = Wp + (size_t)i * 1048576;
    __half* dst = g_WpTh + (size_t)i * 1048576;
    int tx = threadIdx.x, ty = threadIdx.y;   // 32 x 8
    #pragma unroll
    for (int r = 0; r < 32; r += 8)
        t[ty + r][tx] = src[(size_t)(k0 + ty + r) * 1024 + n0 + tx];
    __syncthreads();
    #pragma unroll
    for (int r = 0; r < 32; r += 8)
        dst[(size_t)(n0 + ty + r) * 1024 + k0 + tx] = __float2half_rn(t[tx][ty + r]);
}

// ---------------- qk[b,j] = sum_h Wk[j,h] * q[b,h] ---------------------------------
__global__ void k_qk(const float* __restrict__ Wk)
{
    __shared__ float qsm[8][1024];
    __shared__ float wt[128][17];
    int j0 = blockIdx.x * 128, b0 = blockIdx.y * 8, tid = threadIdx.x;
    for (int idx = tid; idx < 8*1024; idx += 128) {
        int r = idx >> 10, k = idx & 1023;
        qsm[r][k] = g_q[(b0 + r) * HH + k];
    }
    float acc[8] = {0,0,0,0,0,0,0,0};
    for (int h0 = 0; h0 < 1024; h0 += 16) {
        __syncthreads();
        for (int idx = tid; idx < 128*16; idx += 128) {
            int r = idx >> 4, c = idx & 15;
            wt[r][c] = Wk[(size_t)(j0 + r) * HH + h0 + c];
        }
        __syncthreads();
        #pragma unroll
        for (int h = 0; h < 16; h++) {
            float wv = wt[tid][h];
            #pragma unroll
            for (int r = 0; r < 8; r++) acc[r] += qsm[r][h0 + h] * wv;
        }
    }
    #pragma unroll
    for (int r = 0; r < 8; r++) g_qk[(b0 + r) * HH + j0 + tid] = acc[r];
}

// ---------------- scale_importance = softmax(x_last @ Ws + bs) ---------------------
__global__ void k_si(const float* __restrict__ x, const float* __restrict__ Ws,
                     const float* __restrict__ bs)
{
    int b = blockIdx.x, tid = threadIdx.x;   // 128 threads
    __shared__ float xl[HH];
    __shared__ float red[128];
    const float* xp = x + ((size_t)b * SS + SS - 1) * HH;
    for (int k = tid; k < HH; k += 128) xl[k] = xp[k];
    __syncthreads();
    int n = tid & 7, g = tid >> 3;
    float s = 0.f;
    for (int k = g; k < HH; k += 16) s += xl[k] * Ws[k * NSC + n];
    red[tid] = s; __syncthreads();
    for (int st = 8; st >= 1; st >>= 1) {
        if (g < st) red[tid] += red[tid + st * 8];
        __syncthreads();
    }
    if (tid == 0) {
        float l[8], mx = -1e30f;
        #pragma unroll
        for (int j = 0; j < 8; j++) { l[j] = red[j] + bs[j]; mx = fmaxf(mx, l[j]); }
        float sum = 0.f;
        #pragma unroll
        for (int j = 0; j < 8; j++) { l[j] = __expf(l[j] - mx); sum += l[j]; }
        #pragma unroll
        for (int j = 0; j < 8; j++) g_si[b * 8 + j] = l[j] / sum;
    }
}

// ---------------- pass 1: logits (x . qk) + stride-4 block sums --------------------
__global__ void k_pass1(const float* __restrict__ x)
{
    int m = blockIdx.x, b = blockIdx.y, tid = threadIdx.x;  // 256 threads
    const float4* xp = (const float4*)(x + ((size_t)b * SS + m * 4) * HH);
    float4 qk4 = ((const float4*)g_qk)[b * 256 + tid];
    float4 cs = {0.f,0.f,0.f,0.f};
    float dt[4];
    #pragma unroll
    for (int s = 0; s < 4; s++) {
        float4 v = xp[s * 256 + tid];
        cs.x += v.x; cs.y += v.y; cs.z += v.z; cs.w += v.w;
        dt[s] = v.x*qk4.x + v.y*qk4.y + v.z*qk4.z + v.w*qk4.w;
    }
    ((float4*)g_pyr)[((size_t)b * 510 + m) * 256 + tid] = cs;
    #pragma unroll
    for (int o = 16; o; o >>= 1) {
        dt[0] += __shfl_down_sync(0xffffffffu, dt[0], o);
        dt[1] += __shfl_down_sync(0xffffffffu, dt[1], o);
        dt[2] += __shfl_down_sync(0xffffffffu, dt[2], o);
        dt[3] += __shfl_down_sync(0xffffffffu, dt[3], o);
    }
    __shared__ float wr[8][4];
    int lane = tid & 31, warp = tid >> 5;
    if (lane == 0) { wr[warp][0]=dt[0]; wr[warp][1]=dt[1]; wr[warp][2]=dt[2]; wr[warp][3]=dt[3]; }
    __syncthreads();
    if (tid < 4) {
        float s = 0.f;
        #pragma unroll
        for (int w = 0; w < 8; w++) s += wr[w][tid];
        g_logits[b * SS + m * 4 + tid] = s;
    }
}

// ---------------- softmax over S of logits * (1/32) --------------------------------
__global__ void k_softmax()
{
    int b = blockIdx.x, tid = threadIdx.x;   // 256 threads
    __shared__ float red[256];
    float4 v = ((const float4*)g_logits)[b * 256 + tid];
    const float sc = 0.03125f;
    v.x *= sc; v.y *= sc; v.z *= sc; v.w *= sc;
    float mx = fmaxf(fmaxf(v.x, v.y), fmaxf(v.z, v.w));
    red[tid] = mx; __syncthreads();
    for (int st = 128; st; st >>= 1) { if (tid < st) red[tid] = fmaxf(red[tid], red[tid + st]); __syncthreads(); }
    mx = red[0]; __syncthreads();
    float4 e = { __expf(v.x - mx), __expf(v.y - mx), __expf(v.z - mx), __expf(v.w - mx) };
    red[tid] = e.x + e.y + e.z + e.w; __syncthreads();
    for (int st = 128; st; st >>= 1) { if (tid < st) red[tid] += red[tid + st]; __syncthreads(); }
    float inv = 1.f / red[0];
    float4 o = { e.x*inv, e.y*inv, e.z*inv, e.w*inv };
    ((float4*)g_attn)[b * 256 + tid] = o;
}

// ---------------- pass 2: xa[b,h] = sum_s attn[b,s] x[b,s,h] -----------------------
__global__ void k_pass2(const float* __restrict__ x)
{
    int c = blockIdx.x, b = blockIdx.y, tid = threadIdx.x;  // 128 threads
    __shared__ float at[SS];
    for (int i = tid; i < SS; i += 128) at[i] = g_attn[b * SS + i];
    __syncthreads();
    int h = c * 128 + tid;
    const float* xp = x + (size_t)b * SS * HH + h;
    float a0=0.f, a1=0.f, a2=0.f, a3=0.f;
    #pragma unroll 2
    for (int s = 0; s < SS; s += 4) {
        a0 += at[s+0] * xp[(size_t)(s+0) * HH];
        a1 += at[s+1] * xp[(size_t)(s+1) * HH];
        a2 += at[s+2] * xp[(size_t)(s+2) * HH];
        a3 += at[s+3] * xp[(size_t)(s+3) * HH];
    }
    g_xa[b * HH + h] = (a0 + a1) + (a2 + a3);
}

// ---------------- pyramid level l: pooled(half) for scale i=7-l + level l+1 sums ---
__global__ void k_pyr(int l)
{
    int j = blockIdx.x, b = blockIdx.y, tid = threadIdx.x;  // 256 thr, grid.x = Rl-1
    int Rm1 = gridDim.x;
    int i = 7 - l;
    float inv = 1.f / (float)(8 << l);
    const float4* P = (const float4*)g_pyr;
    size_t base = ((size_t)b * 510 + c_loff[l]) * 256;
    float4 r0 = P[base + (size_t)j * 256 + tid];
    float4 r1 = P[base + (size_t)(j + 1) * 256 + tid];
    float4 s = { r0.x + r1.x, r0.y + r1.y, r0.z + r1.z, r0.w + r1.w };
    __half2 h01 = __floats2half2_rn(s.x * inv, s.y * inv);
    __half2 h23 = __floats2half2_rn(s.z * inv, s.w * inv);
    uint2 packed = { *(unsigned*)&h01, *(unsigned*)&h23 };
    ((uint2*)g_pooledh)[(size_t)(c_PO[i] + b * Rm1 + j) * 256 + tid] = packed;
    if (l < 7 && (j & 1) == 0) {
        size_t nbase = ((size_t)b * 510 + c_loff[l + 1]) * 256;
        ((float4*)g_pyr)[nbase + (size_t)(j >> 1) * 256 + tid] = s;
    }
}

// ---------------- feat = tanh(pooled @ Wp[i] + bp[i]) ------------------------------
// mma.sync f16 m16n8k16 (fp32 accum), 128x128 block tile, 256 threads = 8 warps
// (2x4, warp tile 64x32), 4-stage cp.async ring (K-chunk 32 halfs), ldmatrix.x4.
#define KPH 40                         // 32 k halfs + 8 pad
#define STG_H (2 * 128 * KPH)          // halfs per stage (A then B) = 10240
#define F_SMEM_BYTES (4 * STG_H * 2)   // 81920 bytes

__global__ void __launch_bounds__(256, 2) k_feat(const float* __restrict__ bp)
{
    extern __shared__ __align__(16) __half smh[];
    int tid = threadIdx.x, lane = tid & 31, warp = tid >> 5;
    int wm = warp >> 2, wn = warp & 3;          // 2 x 4 warp grid, 64x32 per warp
    int grp = lane >> 2, tg = lane & 3;

    int ty = blockIdx.y;                         // 0..255 -> 128-row tile
    int n0 = blockIdx.x * 128;
    int r256 = ty >> 1;
    int i = r256 ? (32 - __clz(r256)) : 0;       // scale index (padded layout)
    size_t row0 = (size_t)ty * 128;

    const __half* Ab = g_pooledh + row0 * 1024;
    const __half* Bb = g_WpTh + (size_t)i * 1048576 + (size_t)n0 * 1024;

    // ldmatrix per-lane address offsets (bytes)
    int lj = lane >> 3, lr = lane & 7;
    uint32_t a_off = (uint32_t)(((((lj & 1) << 3) + lr) * KPH + ((lj >> 1) << 3)) * 2);
    uint32_t b_off = (uint32_t)(((((lj >> 1) << 3) + lr) * KPH + ((lj & 1) << 3)) * 2);
    uint32_t smbase = (uint32_t)__cvta_generic_to_shared(smh);
    uint32_t awarp = (uint32_t)(wm * 64 * KPH * 2) + a_off;
    uint32_t bwarp = (uint32_t)(wn * 32 * KPH * 2) + b_off;

    float acc[4][4][4];
    #pragma unroll
    for (int a = 0; a < 4; a++)
        #pragma unroll
        for (int b2 = 0; b2 < 4; b2++)
            #pragma unroll
            for (int c = 0; c < 4; c++) acc[a][b2][c] = 0.f;

    auto load_stage = [&](int st, int ch) {
        __half* As = smh + st * STG_H;
        __half* Bs = As + 128 * KPH;
        int k0 = ch * 32;
        #pragma unroll
        for (int j = 0; j < 2; j++) {
            int idx = tid + j * 256;
            int r = idx >> 2, c = (idx & 3) * 8;     // half units
            cp_async16(&As[r * KPH + c], Ab + (size_t)r * 1024 + k0 + c);
            cp_async16(&Bs[r * KPH + c], Bb + (size_t)r * 1024 + k0 + c);
        }
        cp_async_commit();
    };

    load_stage(0, 0);
    load_stage(1, 1);
    load_stage(2, 2);

    for (int ch = 0; ch < 32; ch++) {
        if (ch < 30)       cp_async_wait<2>();
        else if (ch == 30) cp_async_wait<1>();
        else               cp_async_wait<0>();
        __syncthreads();

        if (ch + 3 < 32) load_stage((ch + 3) & 3, ch + 3);

        uint32_t abase = smbase + (uint32_t)((ch & 3) * STG_H * 2) + awarp;
        uint32_t bbase = smbase + (uint32_t)((ch & 3) * STG_H * 2 + 128 * KPH * 2) + bwarp;

        #pragma unroll
        for (int ks = 0; ks < 2; ks++) {             // two k16 steps per chunk
            uint32_t koff = (uint32_t)(ks * 32);     // 16 halfs = 32 bytes
            unsigned a[4][4], bf[4][2];
            #pragma unroll
            for (int mt = 0; mt < 4; mt++)
                ldsm_x4(a[mt][0], a[mt][1], a[mt][2], a[mt][3],
                        abase + (uint32_t)(mt * 16 * KPH * 2) + koff);
            #pragma unroll
            for (int p = 0; p < 2; p++)
                ldsm_x4(bf[2*p][0], bf[2*p][1], bf[2*p+1][0], bf[2*p+1][1],
                        bbase + (uint32_t)(p * 16 * KPH * 2) + koff);
            #pragma unroll
            for (int mt = 0; mt < 4; mt++)
                #pragma unroll
                for (int nt = 0; nt < 4; nt++) {
                    asm volatile(
                        "mma.sync.aligned.m16n8k16.row.col.f32.f16.f16.f32 "
                        "{%0,%1,%2,%3}, {%4,%5,%6,%7}, {%8,%9}, {%0,%1,%2,%3};"
                        : "+f"(acc[mt][nt][0]), "+f"(acc[mt][nt][1]),
                          "+f"(acc[mt][nt][2]), "+f"(acc[mt][nt][3])
                        : "r"(a[mt][0]), "r"(a[mt][1]), "r"(a[mt][2]), "r"(a[mt][3]),
                          "r"(bf[nt][0]), "r"(bf[nt][1]));
                }
        }
    }

    const float* bias = bp + i * 1024 + n0;
    #pragma unroll
    for (int mt = 0; mt < 4; mt++)
        #pragma unroll
        for (int nt = 0; nt < 4; nt++) {
            int row  = (int)row0 + wm * 64 + mt * 16 + grp;
            int cloc = wn * 32 + nt * 8 + tg * 2;
            int col  = n0 + cloc;
            float b0v = bias[cloc], b1v = bias[cloc + 1];
            g_feat[(size_t)row * 1024 + col    ] = tanhf(acc[mt][nt][0] + b0v);
            g_feat[(size_t)row * 1024 + col + 1] = tanhf(acc[mt][nt][1] + b1v);
            g_feat[(size_t)(row + 8) * 1024 + col    ] = tanhf(acc[mt][nt][2] + b0v);
            g_feat[(size_t)(row + 8) * 1024 + col + 1] = tanhf(acc[mt][nt][3] + b1v);
        }
}

// ---------------- per-scale attention: fa = softmax(q.feat/32); ctx = fa.feat ------
__global__ void k_scale_attn()
{
    int i = blockIdx.x, b = blockIdx.y;      // 8 x 64
    int tid = threadIdx.x;                    // 256 threads
    int lane = tid & 31, warp = tid >> 5;
    int n_i = c_n[i];
    size_t rowbase = (size_t)c_PO[i] + (size_t)b * n_i;

    __shared__ float4 qs4[256];
    __shared__ float d[256];
    __shared__ float red[256];

    qs4[tid] = ((const float4*)g_q)[b * 256 + tid];
    __syncthreads();

    const float4* F = (const float4*)g_feat;
    for (int n = warp; n < n_i; n += 8) {
        const float4* fr = F + (rowbase + n) * 256;
        float s = 0.f;
        for (int h = lane; h < 256; h += 32) {
            float4 f = fr[h]; float4 qq = qs4[h];
            s += f.x*qq.x + f.y*qq.y + f.z*qq.z + f.w*qq.w;
        }
        #pragma unroll
        for (int o = 16; o; o >>= 1) s += __shfl_down_sync(0xffffffffu, s, o);
        if (lane == 0) d[n] = s * 0.03125f;
    }
    __syncthreads();

    float val = (tid < n_i) ? d[tid] : -1e30f;
    red[tid] = val; __syncthreads();
    for (int st = 128; st; st >>= 1) { if (tid < st) red[tid] = fmaxf(red[tid], red[tid + st]); __syncthreads(); }
    float mx = red[0]; __syncthreads();
    float e = (tid < n_i) ? __expf(val - mx) : 0.f;
    red[tid] = e; __syncthreads();
    for (int st = 128; st; st >>= 1) { if (tid < st) red[tid] += red[tid + st]; __syncthreads(); }
    float inv = 1.f / red[0];
    __syncthreads();
    if (tid < n_i) d[tid] = e * inv;
    __syncthreads();

    float4 acc = {0.f,0.f,0.f,0.f};
    for (int n = 0; n < n_i; n++) {
        float w = d[n];
        float4 f = F[(rowbase + n) * 256 + tid];
        acc.x += w*f.x; acc.y += w*f.y; acc.z += w*f.z; acc.w += w*f.w;
    }
    ((float4*)g_ctx)[(size_t)(b * 8 + i) * 256 + tid] = acc;
}

// ---------------- out = (bc + sum_i si*ctx_i) @ Wo + bo (combine fused) ------------
__global__ void __launch_bounds__(256) k_out_gemm(const float* __restrict__ Wo,
                                                  const float* __restrict__ bo,
                                                  float* __restrict__ out)
{
    __shared__ float As[8*1024];
    int tid = threadIdx.x;
    int bx = blockIdx.x & 3, by = blockIdx.x >> 2;
    int r0 = by * 8;
    int n  = bx * 256 + tid;
    for (int idx = tid; idx < 8*1024; idx += 256) {
        int r = idx >> 10, k = idx & 1023;
        int row = r0 + r;
        float v = g_bc[(size_t)row * 1024 + k];
        #pragma unroll
        for (int i = 0; i < 8; i++)
            v += g_si[row * 8 + i] * g_ctx[(size_t)(row * 8 + i) * 1024 + k];
        As[r * 1024 + k] = v;
    }
    __syncthreads();
    float acc[8] = {0,0,0,0,0,0,0,0};
    #pragma unroll 4
    for (int k = 0; k < 1024; k++) {
        float bv = Wo[(size_t)k * 1024 + n];
        #pragma unroll
        for (int r = 0; r < 8; r++) acc[r] += As[r * 1024 + k] * bv;
    }
    float bb = bo[n];
    #pragma unroll
    for (int r = 0; r < 8; r++) out[(size_t)(r0 + r) * 1024 + n] = acc[r] + bb;
}

// -----------------------------------------------------------------------------------
extern "C" void kernel_launch(void* const* d_in, const int* in_sizes, int n_in,
                              void* d_out, int out_size)
{
    const float* x  = (const float*)d_in[0];
    const float* Wq = (const float*)d_in[1];
    const float* bq = (const float*)d_in[2];
    const float* Wk = (const float*)d_in[3];
    // bk (d_in[4]) cancels inside softmax — unused
    const float* Wv = (const float*)d_in[5];
    const float* bv = (const float*)d_in[6];
    const float* Wp = (const float*)d_in[7];
    const float* bp = (const float*)d_in[8];
    const float* Ws = (const float*)d_in[9];
    const float* bs = (const float*)d_in[10];
    const float* Wo = (const float*)d_in[11];
    const float* bo = (const float*)d_in[12];
    float* out = (float*)d_out;

    cudaFuncSetAttribute(k_feat, cudaFuncAttributeMaxDynamicSharedMemorySize, F_SMEM_BYTES);

    k_wpt    <<<dim3(32, 32, 8), dim3(32, 8)>>>(Wp);
    k_q_gemm <<<dim3(8, 8), 128>>>(x, Wq, bq);
    k_qk     <<<dim3(8, 8), 128>>>(Wk);
    k_si     <<<64, 128>>>(x, Ws, bs);
    k_pass1  <<<dim3(256, 64), 256>>>(x);
    k_softmax<<<64, 256>>>();
    k_pass2  <<<dim3(8, 64), 128>>>(x);
    k_bc_gemm<<<dim3(8, 8), 128>>>(Wv, bv);
    for (int l = 0; l < 8; l++) {
        int Rl = 256 >> l;
        k_pyr<<<dim3(Rl - 1, 64), 256>>>(l);
    }
    k_feat      <<<dim3(8, 256), 256, F_SMEM_BYTES>>>(bp);
    k_scale_attn<<<dim3(8, 64), 256>>>();
    k_out_gemm  <<<32, 256>>>(Wo, bo, out);
}